// round 14
// baseline (speedup 1.0000x reference)
#include <cuda_runtime.h>
#include <cuda_bf16.h>
#include <cstdint>

// Problem constants
#define B_    256
#define T_    2048
#define F_    64
#define H_    512
#define C_    128

// Partitioning: 64 gate-row chunks (32 rows = 8 h-units) x 2 batch chunks (128) = 128 CTAs
#define NJ    64
#define NCTA  128
#define NTHR  256
#define JTH   8       // h-units per CTA
#define NROW  32      // gate rows per CTA
#define MB    128     // batches per CTA

// SMEM byte offsets
#define OFF_A     0                       // 8 warps x 2 bufs x 4KB = 65536
#define OFF_WF    65536                   // gate weight frags: 36*4*32*16 = 73728
#define OFF_HN    139264                  // 8 warps x 8jj x 16 batches f32 = 4096
#define OFF_DS    143360                  // decoder staging: 8 warps x 512B = 4096
#define OFF_WDF   147456                  // decoder W frags: 16*32*8 = 4096
#define OFF_BSUM  151552                  // 32 f32
#define OFF_BD    151680                  // 128 f32
#define SMEM_BYTES 152192

// ---------------- device globals (static scratch; zero-initialized) ---------
__device__ __nv_bfloat16 g_hhi[2][B_][H_];   // h hi, double buffered
__device__ __nv_bfloat16 g_hlo[2][B_][H_];   // h lo
__device__ float g_part[2][NJ][B_][C_];      // decoder partial logits
__device__ unsigned int g_count = 0;
__device__ volatile unsigned int g_sense = 0;

__device__ __forceinline__ float sigm(float x) { return 1.0f / (1.0f + expf(-x)); }
__device__ __forceinline__ uint32_t sw128(uint32_t off) { return off ^ ((off >> 3) & 0x70); }

__device__ __forceinline__ void pack_hilo(float f0, float f1, uint32_t& hi, uint32_t& lo) {
    __nv_bfloat16 h0 = __float2bfloat16(f0), h1 = __float2bfloat16(f1);
    float r0 = f0 - __bfloat162float(h0), r1 = f1 - __bfloat162float(h1);
    __nv_bfloat16 l0 = __float2bfloat16(r0), l1 = __float2bfloat16(r1);
    hi = (uint32_t)__bfloat16_as_ushort(h0) | ((uint32_t)__bfloat16_as_ushort(h1) << 16);
    lo = (uint32_t)__bfloat16_as_ushort(l0) | ((uint32_t)__bfloat16_as_ushort(l1) << 16);
}

#define LDMX4(r0,r1,r2,r3,addr) \
    asm volatile("ldmatrix.sync.aligned.m8n8.x4.shared.b16 {%0,%1,%2,%3}, [%4];" \
                 : "=r"(r0),"=r"(r1),"=r"(r2),"=r"(r3) : "r"(addr))

#define LDMX2(r0,r1,addr) \
    asm volatile("ldmatrix.sync.aligned.m8n8.x2.shared.b16 {%0,%1}, [%2];" \
                 : "=r"(r0),"=r"(r1) : "r"(addr))

#define MMA16816(d,a0,a1,a2,a3,b0,b1) \
    asm volatile("mma.sync.aligned.m16n8k16.row.col.f32.bf16.bf16.f32 " \
                 "{%0,%1,%2,%3}, {%4,%5,%6,%7}, {%8,%9}, {%0,%1,%2,%3};" \
                 : "+f"(d[0]),"+f"(d[1]),"+f"(d[2]),"+f"(d[3]) \
                 : "r"(a0),"r"(a1),"r"(a2),"r"(a3), "r"(b0),"r"(b1))

__global__ void __launch_bounds__(NTHR, 1) lstm_hmma_kernel(
    const float* __restrict__ X,    // [B, T, F]
    const float* __restrict__ Wih,  // [4H, F]
    const float* __restrict__ Whh,  // [4H, H]
    const float* __restrict__ bih,  // [4H]
    const float* __restrict__ bhh,  // [4H]
    const float* __restrict__ Wd,   // [C, H]
    const float* __restrict__ bd,   // [C]
    float* __restrict__ out)        // [B, T*C]
{
    extern __shared__ char smc[];
    const uint32_t smb = (uint32_t)__cvta_generic_to_shared(smc);
    uint4*  wfrag = (uint4*)(smc + OFF_WF);   // [36][4][32] {bhi0,bhi1,blo0,blo1}
    uint2*  wdf   = (uint2*)(smc + OFF_WDF);  // [16 nt][32 lanes] {bhi,blo}
    float*  bsum  = (float*)(smc + OFF_BSUM); // [32]
    float*  bds   = (float*)(smc + OFF_BD);   // [128]

    const int tid  = threadIdx.x;
    const int cta  = blockIdx.x;
    const int jb   = cta >> 1;           // gate-row chunk 0..63
    const int bb   = cta & 1;            // batch chunk 0..1
    const int J0h  = jb * JTH;
    const int b0   = bb * MB;
    const int wrp  = tid >> 5;           // warp id 0..7 = m-tile
    const int lane = tid & 31;
    const int rloc = lane >> 1;          // warp-local staging row 0..15
    const int seg  = lane & 1;           // k half (32 elems)

    // ---- one-time init: gate weight fragments (bf16 hi/lo, mma frag order) ----
    for (int idx = tid; idx < 36 * 4 * 32; idx += NTHR) {
        int ks = idx >> 7, rem = idx & 127;
        int nt = rem >> 5, l = rem & 31;
        int n = nt * 8 + (l >> 2);                 // gate row 0..31
        int jj = n >> 2, g = n & 3;
        int grow = g * H_ + J0h + jj;              // PyTorch gate order i,f,g,o
        int kA = ks * 16 + (l & 3) * 2;
        float w[4];
        #pragma unroll
        for (int e = 0; e < 4; ++e) {
            int k = kA + (e & 1) + (e >> 1) * 8;
            w[e] = (k < F_) ? Wih[(size_t)grow * F_ + k]
                            : Whh[(size_t)grow * H_ + (k - F_)];
        }
        uint32_t h0, l0, h1, l1;
        pack_hilo(w[0], w[1], h0, l0);
        pack_hilo(w[2], w[3], h1, l1);
        wfrag[idx] = make_uint4(h0, h1, l0, l1);
    }
    // decoder W_d fragments: B frag b0 for k=0..7 (jj), col = c
    for (int idx = tid; idx < 16 * 32; idx += NTHR) {
        int nt = idx >> 5, l = idx & 31;
        int c0 = nt * 8 + (l >> 2);
        int k0 = (l & 3) * 2;
        float w0 = Wd[(size_t)c0 * H_ + J0h + k0];
        float w1 = Wd[(size_t)c0 * H_ + J0h + k0 + 1];
        uint32_t hi, lo;
        pack_hilo(w0, w1, hi, lo);
        wdf[idx] = make_uint2(hi, lo);
    }
    if (tid < NROW) {
        int jj = tid >> 2, g = tid & 3;
        bsum[tid] = bih[g * H_ + J0h + jj] + bhh[g * H_ + J0h + jj];
    }
    if (tid < C_) bds[tid] = bd[tid];
    __syncthreads();

    // bias registers for this thread's 4 jj values
    const int jbit = (lane >> 1) & 1;
    float bi[4], bf[4], bg[4], bo[4];
    #pragma unroll
    for (int nt = 0; nt < 4; ++nt) {
        int jj = 2 * nt + jbit;
        bi[nt] = bsum[jj * 4 + 0]; bf[nt] = bsum[jj * 4 + 1];
        bg[nt] = bsum[jj * 4 + 2]; bo[nt] = bsum[jj * 4 + 3];
    }

    float cst[4] = {0.f, 0.f, 0.f, 0.f};
    const int mloc = (lane >> 2) + ((lane & 1) << 3);   // warp-local batch 0..15
    float* hnw = (float*)(smc + OFF_HN) + wrp * 128;    // [8 jj][16]
    const uint32_t dsw = smb + OFF_DS + wrp * 512;      // hi plane +0, lo plane +256

    // per-warp A buffers
    const uint32_t awarp = smb + OFF_A + wrp * 8192;
    uint32_t swst[4], swld[4];
    #pragma unroll
    for (int j = 0; j < 4; ++j)
        swst[j] = sw128((uint32_t)(rloc * 128 + seg * 64 + j * 16));
    #pragma unroll
    for (int ks = 0; ks < 4; ++ks)
        swld[ks] = sw128((uint32_t)((lane & 15) * 128 + ks * 32 + (lane >> 4) * 16));

    const int myb = b0 + wrp * 16 + rloc;               // this lane's staging batch
    uint4 hr[8];
    int cur = 0;

    // ---- preloop: stage x(t=0) into buf0; prefetch h panel 1 ----
    {
        const uint4* xp = (const uint4*)(X + ((size_t)myb * T_) * F_ + seg * 32);
        uint4 xf[8];
        #pragma unroll
        for (int i = 0; i < 8; ++i) xf[i] = __ldcg(xp + i);
        #pragma unroll
        for (int j = 0; j < 4; ++j) {
            float4 fa = *(float4*)&xf[2 * j], fb = *(float4*)&xf[2 * j + 1];
            uint32_t h0,l0,h1,l1,h2,l2,h3,l3;
            pack_hilo(fa.x, fa.y, h0, l0); pack_hilo(fa.z, fa.w, h1, l1);
            pack_hilo(fb.x, fb.y, h2, l2); pack_hilo(fb.z, fb.w, h3, l3);
            asm volatile("st.shared.v4.b32 [%0], {%1,%2,%3,%4};"
                         :: "r"(awarp + swst[j]), "r"(h0),"r"(h1),"r"(h2),"r"(h3));
            asm volatile("st.shared.v4.b32 [%0], {%1,%2,%3,%4};"
                         :: "r"(awarp + 2048 + swst[j]), "r"(l0),"r"(l1),"r"(l2),"r"(l3));
        }
        #pragma unroll
        for (int j = 0; j < 4; ++j) {
            hr[j]     = __ldcg((const uint4*)&g_hhi[0][myb][seg * 32 + j * 8]);
            hr[4 + j] = __ldcg((const uint4*)&g_hlo[0][myb][seg * 32 + j * 8]);
        }
    }
    __syncthreads();

    for (int t = 0; t < T_; ++t) {
        const int par = t & 1;

        float acc[4][4];
        #pragma unroll
        for (int nt = 0; nt < 4; ++nt)
            #pragma unroll
            for (int i = 0; i < 4; ++i) acc[nt][i] = 0.f;

        // ---- gates GEMM: 9 panels of K=64, fully warp-local ----
        #pragma unroll 1
        for (int p = 0; p < 9; ++p) {
            const uint32_t bufc = awarp + cur * 4096;
            const uint32_t bufn = awarp + (cur ^ 1) * 4096;
            __syncwarp();
            if (p < 8) {
                #pragma unroll
                for (int j = 0; j < 4; ++j) {
                    uint4 h = hr[j], l = hr[4 + j];
                    asm volatile("st.shared.v4.b32 [%0], {%1,%2,%3,%4};"
                                 :: "r"(bufn + swst[j]), "r"(h.x),"r"(h.y),"r"(h.z),"r"(h.w));
                    asm volatile("st.shared.v4.b32 [%0], {%1,%2,%3,%4};"
                                 :: "r"(bufn + 2048 + swst[j]), "r"(l.x),"r"(l.y),"r"(l.z),"r"(l.w));
                }
            } else if (t + 1 < T_) {
                #pragma unroll
                for (int j = 0; j < 4; ++j) {
                    float4 fa = *(float4*)&hr[2 * j], fb = *(float4*)&hr[2 * j + 1];
                    uint32_t h0,l0,h1,l1,h2,l2,h3,l3;
                    pack_hilo(fa.x, fa.y, h0, l0); pack_hilo(fa.z, fa.w, h1, l1);
                    pack_hilo(fb.x, fb.y, h2, l2); pack_hilo(fb.z, fb.w, h3, l3);
                    asm volatile("st.shared.v4.b32 [%0], {%1,%2,%3,%4};"
                                 :: "r"(bufn + swst[j]), "r"(h0),"r"(h1),"r"(h2),"r"(h3));
                    asm volatile("st.shared.v4.b32 [%0], {%1,%2,%3,%4};"
                                 :: "r"(bufn + 2048 + swst[j]), "r"(l0),"r"(l1),"r"(l2),"r"(l3));
                }
            }
            __syncwarp();

            if (p <= 6) {
                int kb = (p + 1) * 64 + seg * 32;
                #pragma unroll
                for (int j = 0; j < 4; ++j) {
                    hr[j]     = __ldcg((const uint4*)&g_hhi[par][myb][kb + j * 8]);
                    hr[4 + j] = __ldcg((const uint4*)&g_hlo[par][myb][kb + j * 8]);
                }
            } else if (p == 7 && t + 1 < T_) {
                const uint4* xp = (const uint4*)(X + ((size_t)myb * T_ + (t + 1)) * F_ + seg * 32);
                #pragma unroll
                for (int i = 0; i < 8; ++i) hr[i] = __ldcg(xp + i);
            }

            #pragma unroll
            for (int ks = 0; ks < 4; ++ks) {
                uint32_t ah0, ah1, ah2, ah3, al0, al1, al2, al3;
                LDMX4(ah0, ah1, ah2, ah3, bufc + swld[ks]);
                LDMX4(al0, al1, al2, al3, bufc + 2048 + swld[ks]);
                const uint4* wf = &wfrag[((p * 4 + ks) * 4) * 32 + lane];
                #pragma unroll
                for (int nt = 0; nt < 4; ++nt) {
                    uint4 b = wf[nt * 32];
                    MMA16816(acc[nt], ah0, ah1, ah2, ah3, b.x, b.y);
                    MMA16816(acc[nt], al0, al1, al2, al3, b.x, b.y);
                    MMA16816(acc[nt], ah0, ah1, ah2, ah3, b.z, b.w);
                }
            }
            cur ^= 1;
        }

        // ---- cell update: reassemble quads via lane-pair shuffles ----
        {
            const int odd = lane & 1;
            #pragma unroll
            for (int nt = 0; nt < 4; ++nt) {
                float t0 = __shfl_xor_sync(0xffffffffu, acc[nt][0], 1);
                float t1 = __shfl_xor_sync(0xffffffffu, acc[nt][1], 1);
                float t2 = __shfl_xor_sync(0xffffffffu, acc[nt][2], 1);
                float t3 = __shfl_xor_sync(0xffffffffu, acc[nt][3], 1);
                float pi = odd ? t2 : acc[nt][0];
                float pf = odd ? t3 : acc[nt][1];
                float pg = odd ? acc[nt][2] : t0;
                float po = odd ? acc[nt][3] : t1;
                pi += bi[nt]; pf += bf[nt]; pg += bg[nt]; po += bo[nt];
                float iv = sigm(pi), fv = sigm(pf), gv = tanhf(pg), ov = sigm(po);
                float cn = fv * cst[nt] + iv * gv;
                cst[nt] = cn;
                hnw[(2 * nt + jbit) * 16 + mloc] = ov * tanhf(cn);
            }
        }
        __syncwarp();

        // ---- lanes 0-15: decoder staging (relu'd bf16 hi/lo);
        //      lanes 16-31: raw h pack + global writeback ----
        if (lane < 16) {
            int r = lane;
            float f[8];
            #pragma unroll
            for (int kk = 0; kk < 8; ++kk) f[kk] = fmaxf(hnw[kk * 16 + r], 0.f);
            uint32_t dh[4], dl[4];
            #pragma unroll
            for (int j = 0; j < 4; ++j) pack_hilo(f[2 * j], f[2 * j + 1], dh[j], dl[j]);
            asm volatile("st.shared.v4.b32 [%0], {%1,%2,%3,%4};"
                         :: "r"(dsw + r * 16), "r"(dh[0]),"r"(dh[1]),"r"(dh[2]),"r"(dh[3]));
            asm volatile("st.shared.v4.b32 [%0], {%1,%2,%3,%4};"
                         :: "r"(dsw + 256 + r * 16), "r"(dl[0]),"r"(dl[1]),"r"(dl[2]),"r"(dl[3]));
        } else {
            int r = lane - 16;
            float f[8];
            #pragma unroll
            for (int kk = 0; kk < 8; ++kk) f[kk] = hnw[kk * 16 + r];
            uint32_t ph[4], pl[4];
            #pragma unroll
            for (int j = 0; j < 4; ++j) pack_hilo(f[2 * j], f[2 * j + 1], ph[j], pl[j]);
            int b = b0 + wrp * 16 + r;
            *(uint4*)&g_hhi[par ^ 1][b][J0h] = make_uint4(ph[0], ph[1], ph[2], ph[3]);
            *(uint4*)&g_hlo[par ^ 1][b][J0h] = make_uint4(pl[0], pl[1], pl[2], pl[3]);
        }
        __syncwarp();

        // ---- decoder GEMM via HMMA: [16 batches x 8k] @ [8k x 128c] ----
        {
            uint32_t a0h, a1h, a0l, a1l;
            LDMX2(a0h, a1h, dsw + (lane & 15) * 16);
            LDMX2(a0l, a1l, dsw + 256 + (lane & 15) * 16);
            const int prow = b0 + wrp * 16 + (lane >> 2);
            const int pcol = (lane & 3) * 2;
            #pragma unroll
            for (int nt = 0; nt < 16; ++nt) {
                uint2 wv = wdf[nt * 32 + lane];
                float d[4] = {0.f, 0.f, 0.f, 0.f};
                MMA16816(d, a0h, a1h, 0u, 0u, wv.x, 0u);
                MMA16816(d, a0l, a1l, 0u, 0u, wv.x, 0u);
                MMA16816(d, a0h, a1h, 0u, 0u, wv.y, 0u);
                *(float2*)&g_part[par][jb][prow][nt * 8 + pcol]     = make_float2(d[0], d[1]);
                *(float2*)&g_part[par][jb][prow + 8][nt * 8 + pcol] = make_float2(d[2], d[3]);
            }
        }

        // ---- grid-wide sync (sense-reversing) ----
        {
            unsigned target = (unsigned)((t & 1) ^ 1);
            __syncthreads();
            if (tid == 0) {
                __threadfence();
                unsigned v = atomicAdd(&g_count, 1u);
                if (v == NCTA - 1) {
                    g_count = 0;
                    __threadfence();
                    g_sense = target;
                } else {
                    while (g_sense != target) { __nanosleep(64); }
                }
                __threadfence();
            }
            __syncthreads();
        }

        // ---- prefetch next step's h panel 1 (now published) ----
        if (t + 1 < T_) {
            #pragma unroll
            for (int j = 0; j < 4; ++j) {
                hr[j]     = __ldcg((const uint4*)&g_hhi[par ^ 1][myb][seg * 32 + j * 8]);
                hr[4 + j] = __ldcg((const uint4*)&g_hlo[par ^ 1][myb][seg * 32 + j * 8]);
            }
        }

        // ---- phase 4 (warps 0-1 ONLY; warps 2-7 run ahead into next GEMM) ----
        if (wrp < 2) {
            const int b = cta * 2 + wrp;
            float v[4];
            #pragma unroll
            for (int j = 0; j < 4; ++j) v[j] = bds[lane + 32 * j];
            #pragma unroll 8
            for (int j2 = 0; j2 < NJ; ++j2) {
                const float* pp = &g_part[par][j2][b][0];
                #pragma unroll
                for (int j = 0; j < 4; ++j) v[j] += __ldcg(pp + lane + 32 * j);
            }
            float m = fmaxf(fmaxf(v[0], v[1]), fmaxf(v[2], v[3]));
            #pragma unroll
            for (int o = 16; o; o >>= 1)
                m = fmaxf(m, __shfl_xor_sync(0xffffffffu, m, o));
            float e[4], s = 0.f;
            #pragma unroll
            for (int j = 0; j < 4; ++j) { e[j] = expf(v[j] - m); s += e[j]; }
            #pragma unroll
            for (int o = 16; o; o >>= 1)
                s += __shfl_xor_sync(0xffffffffu, s, o);
            float inv = 1.0f / s;
            #pragma unroll
            for (int j = 0; j < 4; ++j)
                out[(size_t)b * (T_ * C_) + (size_t)t * C_ + lane + 32 * j] = e[j] * inv;
        }
    }

    // ---- restore parity-0 h to zeros so every launch/replay is identical ----
    if (tid < MB) {
        *(uint4*)&g_hhi[0][b0 + tid][J0h] = make_uint4(0, 0, 0, 0);
    } else {
        *(uint4*)&g_hlo[0][b0 + (tid - MB)][J0h] = make_uint4(0, 0, 0, 0);
    }
}

extern "C" void kernel_launch(void* const* d_in, const int* in_sizes, int n_in,
                              void* d_out, int out_size) {
    (void)in_sizes; (void)n_in; (void)out_size;
    const float* x   = (const float*)d_in[0];
    const float* Wih = (const float*)d_in[1];
    const float* Whh = (const float*)d_in[2];
    const float* bih = (const float*)d_in[3];
    const float* bhh = (const float*)d_in[4];
    const float* Wd  = (const float*)d_in[5];
    const float* bd  = (const float*)d_in[6];
    float* out = (float*)d_out;

    cudaFuncSetAttribute(lstm_hmma_kernel,
                         cudaFuncAttributeMaxDynamicSharedMemorySize, SMEM_BYTES);
    lstm_hmma_kernel<<<NCTA, NTHR, SMEM_BYTES>>>(x, Wih, Whh, bih, bhh, Wd, bd, out);
}